// round 12
// baseline (speedup 1.0000x reference)
#include <cuda_runtime.h>
#include <cstdint>

#define B_   2
#define A_   512
#define T_   512
#define F_   128
#define RBF_ 25
#define TBLK 64
#define NBLK (T_/TBLK)

// Precomputed y = x @ Win, [B,A,F]
__device__ __align__(16) float g_y[B_ * A_ * F_];

// ---------------- smem layout (float offsets) ----------------
#define OFF_WF1 0        // [32][136] tf32          4352
#define OFF_BF1 4352     // 128
#define OFF_RS  4480     // 2 x [64][36] raw f32    4608 (buf stride 2304)
#define OFF_NJ  9088     // 2 x 64 int
#define OFF_NK  9216     // 2 x 64 int
#define OFF_MSK 9344     // 2 x 64 f32
#define OFF_GS  9472     // 128
#define OFF_PRT 9600     // 2*128
#define OFF_ACC 9856     // 128
#define OFF_H1  9984     // 2 x [64][136] tf32 (buf stride 8704); Wf2 overlay at end
#define OFF_GT  27392    // 2 x [128][68] tf32 (buf stride 8704)
#define SMEM_FLOATS 44800
#define SMEM_BYTES  (SMEM_FLOATS * 4)

#define BUFH 8704
#define BUFR 2304

#define LN2 0.69314718055994530942f

static __device__ __forceinline__ float ssp(float v) {
    float e = __expf(-fabsf(v));
    return fmaxf(v, 0.0f) + LN2 * __log2f(1.0f + e) - LN2;
}
static __device__ __forceinline__ uint32_t f2t(float f) {
    uint32_t r;
    asm("cvt.rna.tf32.f32 %0, %1;" : "=r"(r) : "f"(f));
    return r;
}
static __device__ __forceinline__ void mma8(float* d, const uint32_t* a,
                                            uint32_t b0, uint32_t b1) {
    asm volatile(
        "mma.sync.aligned.m16n8k8.row.col.f32.tf32.tf32.f32 "
        "{%0,%1,%2,%3}, {%4,%5,%6,%7}, {%8,%9}, {%0,%1,%2,%3};"
        : "+f"(d[0]), "+f"(d[1]), "+f"(d[2]), "+f"(d[3])
        : "r"(a[0]), "r"(a[1]), "r"(a[2]), "r"(a[3]),
          "r"(b0), "r"(b1));
}
static __device__ __forceinline__ uint32_t smem_u32(const void* p) {
    uint32_t a;
    asm("{ .reg .u64 t; cvta.to.shared.u64 t, %1; cvt.u32.u64 %0, t; }"
        : "=r"(a) : "l"(p));
    return a;
}
#define CP_ASYNC4(dst, src) \
    asm volatile("cp.async.ca.shared.global [%0], [%1], 4;" \
                 :: "r"(dst), "l"(src) : "memory")
#define CP_COMMIT() asm volatile("cp.async.commit_group;" ::: "memory")
#define CP_WAIT0()  asm volatile("cp.async.wait_group 0;" ::: "memory")
#define CP_WAIT1()  asm volatile("cp.async.wait_group 1;" ::: "memory")
// named barriers: FULL[s] = 1+s (joint bar.sync, 512),
//                 EMPTY[s] = 3+s (consumer arrive / producer sync, 512),
//                 producers-only = 5 (256)
#define BAR_SYNC(id, n) asm volatile("bar.sync %0, %1;"   :: "r"(id), "r"(n) : "memory")
#define BAR_ARRV(id, n) asm volatile("bar.arrive %0, %1;" :: "r"(id), "r"(n) : "memory")

// ---------------------------------------------------------------------------
// Kernel 1: y[ba,f] = sum_i x[ba,i] * Win[i,f]
// ---------------------------------------------------------------------------
__global__ __launch_bounds__(128) void y_kernel(const float* __restrict__ x,
                                                const float* __restrict__ Win) {
    int ba = blockIdx.x, f = threadIdx.x;
    __shared__ float xs[F_];
    xs[f] = x[ba * F_ + f];
    __syncthreads();
    float acc = 0.0f;
#pragma unroll 8
    for (int i = 0; i < F_; i++) acc = fmaf(xs[i], Win[i * F_ + f], acc);
    g_y[ba * F_ + f] = acc;
}

// ---------------------------------------------------------------------------
// Prefetch one 64-triplet block into buffer par. Producer threads (0..255).
// ---------------------------------------------------------------------------
static __device__ __forceinline__ void issue_prefetch(
    uint32_t sb, int te, uint32_t t0g, int par,
    const float* __restrict__ r_ij,
    const int* __restrict__ nbr_j, const int* __restrict__ nbr_k,
    const float* __restrict__ mask)
{
    const uint32_t rsb = sb + (uint32_t)(OFF_RS + par * BUFR) * 4u;
#pragma unroll
    for (int j = 0; j < 8; j++) {
        uint32_t idx = (uint32_t)te + j * 256;
        uint32_t t = idx >> 5, r = idx & 31;
        if (r < RBF_)
            CP_ASYNC4(rsb + (t * 36 + r) * 4, r_ij + (size_t)(t0g + t) * RBF_ + r);
    }
    if (te < 64)
        CP_ASYNC4(sb + (OFF_NJ + par * 64 + te) * 4, nbr_j + t0g + te);
    else if (te < 128)
        CP_ASYNC4(sb + (OFF_NK + par * 64 + (te - 64)) * 4, nbr_k + t0g + (te - 64));
    else if (te < 192)
        CP_ASYNC4(sb + (OFF_MSK + par * 64 + (te - 128)) * 4, mask + t0g + (te - 128));
    CP_COMMIT();
}

// ---------------------------------------------------------------------------
// Pipelined fused kernel. One CTA per (b,a). 512 threads = 16 warps.
//   producers (warps 0-7):  stage-1 (w0-3) + gather (w4-7), block b+1
//   consumers (warps 8-15): stage-2 MMAs on block b  (double-buffered H1/GT)
// FULL handoff = joint bar.sync (HW-fenced, drains STS).
// EMPTY handoff = consumer bar.arrive (reads only) / producer bar.sync.
// ---------------------------------------------------------------------------
__global__ __launch_bounds__(512, 1) void cfconv_mma(
    const float* __restrict__ r_ij,
    const float* __restrict__ mask,
    const float* __restrict__ Wf1,
    const float* __restrict__ bf1,
    const float* __restrict__ Wf2,
    const float* __restrict__ bf2,
    const float* __restrict__ Wout,
    const float* __restrict__ bout,
    const int*   __restrict__ nbr_j,
    const int*   __restrict__ nbr_k,
    float*       __restrict__ out)
{
    extern __shared__ float sm[];
    uint32_t* smu = (uint32_t*)sm;
    const uint32_t sb = smem_u32(sm);

    const int tid  = threadIdx.x;
    const int wid  = tid >> 5;
    const int lane = tid & 31;
    const int gr   = lane >> 2;
    const int t4   = lane & 3;
    const int ba   = blockIdx.x;
    const int b    = ba / A_;

    // zero RS pad cols [25,36) for both buffers
    for (int i = tid; i < 2 * TBLK * 11; i += 512) {
        int buf = i / (TBLK * 11);
        int k = i - buf * (TBLK * 11);
        int t = k / 11, r = 25 + (k - t * 11);
        sm[OFF_RS + buf * BUFR + t * 36 + r] = 0.0f;
    }
    if (tid < 256)
        issue_prefetch(sb, tid, (uint32_t)ba * T_, 0, r_ij, nbr_j, nbr_k, mask);

    // one-time weights
    for (int i = tid; i < 32 * F_; i += 512) {
        int k = i >> 7, g = i & 127;
        float v = (k < RBF_) ? Wf1[k * F_ + g] : 0.0f;
        smu[OFF_WF1 + k * 136 + g] = f2t(v);
    }
    if (tid < 128) sm[OFF_BF1 + tid] = bf1[tid];
    __syncthreads();

    float gsum = 0.0f;                 // gather warps
    float P[2][8][4];                  // consumer warps
#pragma unroll
    for (int mt = 0; mt < 2; mt++)
#pragma unroll
        for (int nt = 0; nt < 8; nt++)
#pragma unroll
            for (int j = 0; j < 4; j++) P[mt][nt][j] = 0.0f;

    if (tid < 256) {
        // ================= PRODUCERS =================
        for (int blk = 0; blk < NBLK; blk++) {
            const int s = blk & 1;
            const uint32_t t0g = (uint32_t)ba * T_ + blk * TBLK;

            if (blk + 1 < NBLK) {
                issue_prefetch(sb, tid, t0g + TBLK, s ^ 1,
                               r_ij, nbr_j, nbr_k, mask);
                CP_WAIT1();
            } else {
                CP_WAIT0();
            }
            BAR_SYNC(5, 256);                  // block-s inputs visible to all producers
            if (blk >= 2) BAR_SYNC(3 + s, 512); // wait consumers freed buffer s

            if (tid < 128) {
                // ---- stage 1: H1[s] = ssp(R @ Wf1 + bf1), 16 rows/warp ----
                const int tb = wid * 16;
                const uint32_t rsO = OFF_RS + (uint32_t)s * BUFR;
                const uint32_t* rA = &smu[rsO + (tb + gr) * 36 + t4];
                const uint32_t* rB = &smu[rsO + (tb + gr + 8) * 36 + t4];
                uint32_t a[4][4];
#pragma unroll
                for (int k = 0; k < 4; k++) {
                    a[k][0] = rA[k * 8];
                    a[k][1] = rB[k * 8];
                    a[k][2] = rA[k * 8 + 4];
                    a[k][3] = rB[k * 8 + 4];
                }
                const uint32_t h0 = OFF_H1 + s * BUFH + (tb + gr) * 136;
                const uint32_t h1r = h0 + 8 * 136;
#pragma unroll
                for (int nt = 0; nt < 16; nt++) {
                    float sacc[4] = {0.f, 0.f, 0.f, 0.f};
                    const uint32_t* wB = &smu[OFF_WF1 + t4 * 136 + nt * 8 + gr];
#pragma unroll
                    for (int k = 0; k < 4; k++)
                        mma8(sacc, a[k], wB[(k * 8) * 136], wB[(k * 8 + 4) * 136]);
                    int c = nt * 8 + 2 * t4;
                    float bc0 = sm[OFF_BF1 + c];
                    float bc1 = sm[OFF_BF1 + c + 1];
                    smu[h0 + c]      = f2t(ssp(sacc[0] + bc0));
                    smu[h0 + c + 1]  = f2t(ssp(sacc[1] + bc1));
                    smu[h1r + c]     = f2t(ssp(sacc[2] + bc0));
                    smu[h1r + c + 1] = f2t(ssp(sacc[3] + bc1));
                }
            } else {
                // ---- gather: GT[s][f][t] = yj*yk*mask, thread per f ----
                const uint32_t f = tid - 128;
                const float* yb  = g_y + (uint32_t)b * (A_ * F_) + f;
                const int*   sNj = (const int*)(sm + OFF_NJ + s * 64);
                const int*   sNk = (const int*)(sm + OFF_NK + s * 64);
                const float* sM  = sm + OFF_MSK + s * 64;
                const uint32_t gb = OFF_GT + s * BUFH + f * 68;
#pragma unroll
                for (int tt = 0; tt < TBLK; tt += 8) {
                    float vj[8], vk[8];
#pragma unroll
                    for (int w = 0; w < 8; w++) {
                        vj[w] = yb[(uint32_t)sNj[tt + w] * F_];
                        vk[w] = yb[(uint32_t)sNk[tt + w] * F_];
                    }
                    uint4 q0, q1;
                    uint32_t* g0 = (uint32_t*)&q0;
                    uint32_t* g1 = (uint32_t*)&q1;
#pragma unroll
                    for (int w = 0; w < 8; w++) {
                        float gv = vj[w] * vk[w] * sM[tt + w];
                        gsum += gv;
                        if (w < 4) g0[w] = f2t(gv);
                        else       g1[w - 4] = f2t(gv);
                    }
                    *(uint4*)&smu[gb + tt]     = q0;
                    *(uint4*)&smu[gb + tt + 4] = q1;
                }
            }
            BAR_SYNC(1 + s, 512);              // FULL rendezvous (fenced handoff)
        }
    } else {
        // ================= CONSUMERS =================
        const int cw = wid - 8;
        const int m0 = (cw & 3) * 32, n0 = (cw >> 2) * 64;
        for (int blk = 0; blk < NBLK; blk++) {
            const int s = blk & 1;
            BAR_SYNC(1 + s, 512);              // FULL rendezvous
            const uint32_t gbase = OFF_GT + s * BUFH + (m0 + gr) * 68 + t4;
            const uint32_t hbase = OFF_H1 + s * BUFH + t4 * 136 + n0 + gr;
#pragma unroll
            for (int k = 0; k < 8; k++) {
                const int kk = k * 8;
                uint32_t a0[4], a1[4];
                a0[0] = smu[gbase + kk];
                a0[1] = smu[gbase + 8 * 68 + kk];
                a0[2] = smu[gbase + kk + 4];
                a0[3] = smu[gbase + 8 * 68 + kk + 4];
                a1[0] = smu[gbase + 16 * 68 + kk];
                a1[1] = smu[gbase + 24 * 68 + kk];
                a1[2] = smu[gbase + 16 * 68 + kk + 4];
                a1[3] = smu[gbase + 24 * 68 + kk + 4];
#pragma unroll
                for (int nt = 0; nt < 8; nt++) {
                    uint32_t b0 = smu[hbase + kk * 136 + nt * 8];
                    uint32_t b1 = smu[hbase + (kk + 4) * 136 + nt * 8];
                    mma8(P[0][nt], a0, b0, b1);
                    mma8(P[1][nt], a1, b0, b1);
                }
            }
            BAR_ARRV(3 + s, 512);              // buffer s EMPTY (reads only)
        }
    }

    // ---- epilogue ----
    if (tid >= 128 && tid < 256) sm[OFF_GS + (tid - 128)] = gsum;
    __syncthreads();                            // join; H1 buffers now free
    for (int i = tid; i < F_ * F_; i += 512) sm[OFF_H1 + i] = Wf2[i];
    __syncthreads();

    if (tid >= 256) {
        const int cw = wid - 8;
        const int m0 = (cw & 3) * 32, n0 = (cw >> 2) * 64;
        const int wn = cw >> 2;
#pragma unroll
        for (int mt = 0; mt < 2; mt++) {
            int f0 = m0 + mt * 16 + gr;
            int f1 = f0 + 8;
            float p0 = 0.0f, p1 = 0.0f;
#pragma unroll
            for (int nt = 0; nt < 8; nt++) {
                int c = n0 + nt * 8 + 2 * t4;
                p0 += P[mt][nt][0] * sm[OFF_H1 + c * F_ + f0]
                    + P[mt][nt][1] * sm[OFF_H1 + (c + 1) * F_ + f0];
                p1 += P[mt][nt][2] * sm[OFF_H1 + c * F_ + f1]
                    + P[mt][nt][3] * sm[OFF_H1 + (c + 1) * F_ + f1];
            }
            p0 += __shfl_xor_sync(0xFFFFFFFFu, p0, 1);
            p0 += __shfl_xor_sync(0xFFFFFFFFu, p0, 2);
            p1 += __shfl_xor_sync(0xFFFFFFFFu, p1, 1);
            p1 += __shfl_xor_sync(0xFFFFFFFFu, p1, 2);
            if (t4 == 0) {
                sm[OFF_PRT + wn * F_ + f0] = p0;
                sm[OFF_PRT + wn * F_ + f1] = p1;
            }
        }
    }
    __syncthreads();

    if (tid < 128) {
        float acc = sm[OFF_PRT + tid] + sm[OFF_PRT + F_ + tid]
                  + bf2[tid] * sm[OFF_GS + tid];
        sm[OFF_ACC + tid] = acc;
    }
    __syncthreads();

    if (tid < 128) {
        float o = bout[tid];
#pragma unroll 8
        for (int g = 0; g < F_; g++)
            o = fmaf(sm[OFF_ACC + g], Wout[g * F_ + tid], o);
        out[(uint32_t)ba * F_ + tid] = ssp(o);
    }
}

// ---------------------------------------------------------------------------
extern "C" void kernel_launch(void* const* d_in, const int* in_sizes, int n_in,
                              void* d_out, int out_size)
{
    const float* x     = (const float*)d_in[0];
    const float* r_ij  = (const float*)d_in[1];
    const float* mask  = (const float*)d_in[2];
    const float* Wf1   = (const float*)d_in[3];
    const float* bf1   = (const float*)d_in[4];
    const float* Wf2   = (const float*)d_in[5];
    const float* bf2   = (const float*)d_in[6];
    const float* Win   = (const float*)d_in[7];
    const float* Wout  = (const float*)d_in[8];
    const float* bout  = (const float*)d_in[9];
    const int*   nbr_j = (const int*)d_in[10];
    const int*   nbr_k = (const int*)d_in[11];
    float* out = (float*)d_out;

    cudaFuncSetAttribute(cfconv_mma,
                         cudaFuncAttributeMaxDynamicSharedMemorySize,
                         SMEM_BYTES);

    y_kernel<<<B_ * A_, 128>>>(x, Win);
    cfconv_mma<<<B_ * A_, 512, SMEM_BYTES>>>(
        r_ij, mask, Wf1, bf1, Wf2, bf2, Wout, bout, nbr_j, nbr_k, out);
}

// round 13
// speedup vs baseline: 1.2909x; 1.2909x over previous
#include <cuda_runtime.h>
#include <cstdint>

#define B_   2
#define A_   512
#define T_   512
#define F_   128
#define RBF_ 25
#define TBLK 64
#define NBLK (T_/TBLK)

// Precomputed y = x @ Win, [B,A,F]
__device__ __align__(16) float g_y[B_ * A_ * F_];

// ---------------- smem layout (float offsets) ----------------
#define OFF_WF1 0        // [32][136] tf32          4352
#define OFF_BF1 4352     // 128
#define OFF_RS  4480     // 2 x [64][36] raw f32    4608 (buf stride 2304)
#define OFF_NJ  9088     // 2 x 64 int
#define OFF_NK  9216     // 2 x 64 int
#define OFF_MSK 9344     // 2 x 64 f32
#define OFF_GS  9472     // 128
#define OFF_PRT 9600     // 2*128
#define OFF_ACC 9856     // 128
#define OFF_H1  9984     // [64][136] tf32  (t x g)  8704   } contiguous 17408
#define OFF_GT  18688    // [128][68] tf32  (f x t)  8704   }  -> Wf2 overlay
#define SMEM_FLOATS 27392
#define SMEM_BYTES  (SMEM_FLOATS * 4)   // 109568 B -> 2 CTAs/SM

#define BUFR 2304

#define LN2 0.69314718055994530942f

static __device__ __forceinline__ float ssp(float v) {
    float e = __expf(-fabsf(v));
    return fmaxf(v, 0.0f) + LN2 * __log2f(1.0f + e) - LN2;
}
static __device__ __forceinline__ uint32_t f2t(float f) {
    uint32_t r;
    asm("cvt.rna.tf32.f32 %0, %1;" : "=r"(r) : "f"(f));
    return r;
}
static __device__ __forceinline__ void mma8(float* d, const uint32_t* a,
                                            uint32_t b0, uint32_t b1) {
    asm volatile(
        "mma.sync.aligned.m16n8k8.row.col.f32.tf32.tf32.f32 "
        "{%0,%1,%2,%3}, {%4,%5,%6,%7}, {%8,%9}, {%0,%1,%2,%3};"
        : "+f"(d[0]), "+f"(d[1]), "+f"(d[2]), "+f"(d[3])
        : "r"(a[0]), "r"(a[1]), "r"(a[2]), "r"(a[3]),
          "r"(b0), "r"(b1));
}
static __device__ __forceinline__ uint32_t smem_u32(const void* p) {
    uint32_t a;
    asm("{ .reg .u64 t; cvta.to.shared.u64 t, %1; cvt.u32.u64 %0, t; }"
        : "=r"(a) : "l"(p));
    return a;
}
#define CP_ASYNC4(dst, src) \
    asm volatile("cp.async.ca.shared.global [%0], [%1], 4;" \
                 :: "r"(dst), "l"(src) : "memory")
#define CP_COMMIT() asm volatile("cp.async.commit_group;" ::: "memory")
#define CP_WAIT0()  asm volatile("cp.async.wait_group 0;" ::: "memory")
#define CP_WAIT1()  asm volatile("cp.async.wait_group 1;" ::: "memory")

// ---------------------------------------------------------------------------
// Kernel 1: y[ba,f] = sum_i x[ba,i] * Win[i,f]
// ---------------------------------------------------------------------------
__global__ __launch_bounds__(128) void y_kernel(const float* __restrict__ x,
                                                const float* __restrict__ Win) {
    int ba = blockIdx.x, f = threadIdx.x;
    __shared__ float xs[F_];
    xs[f] = x[ba * F_ + f];
    __syncthreads();
    float acc = 0.0f;
#pragma unroll 8
    for (int i = 0; i < F_; i++) acc = fmaf(xs[i], Win[i * F_ + f], acc);
    g_y[ba * F_ + f] = acc;
}

// ---------------------------------------------------------------------------
// Prefetch one 64-triplet block into buffer par via cp.async. 256 threads.
// ---------------------------------------------------------------------------
static __device__ __forceinline__ void issue_prefetch(
    uint32_t sb, int tid, uint32_t t0g, int par,
    const float* __restrict__ r_ij,
    const int* __restrict__ nbr_j, const int* __restrict__ nbr_k,
    const float* __restrict__ mask)
{
    const uint32_t rsb = sb + (uint32_t)(OFF_RS + par * BUFR) * 4u;
#pragma unroll
    for (int j = 0; j < 8; j++) {
        uint32_t idx = (uint32_t)tid + j * 256;
        uint32_t t = idx >> 5, r = idx & 31;
        if (r < RBF_)
            CP_ASYNC4(rsb + (t * 36 + r) * 4, r_ij + (size_t)(t0g + t) * RBF_ + r);
    }
    if (tid < 64)
        CP_ASYNC4(sb + (OFF_NJ + par * 64 + tid) * 4, nbr_j + t0g + tid);
    else if (tid < 128)
        CP_ASYNC4(sb + (OFF_NK + par * 64 + (tid - 64)) * 4, nbr_k + t0g + (tid - 64));
    else if (tid < 192)
        CP_ASYNC4(sb + (OFF_MSK + par * 64 + (tid - 128)) * 4, mask + t0g + (tid - 128));
    CP_COMMIT();
}

// ---------------------------------------------------------------------------
// Fused kernel. One 256-thread CTA per (b,a); 2 CTAs/SM.
// Per 64-triplet block:
//   warps 0-3: stage-1 MMA  H1 = ssp(R @ Wf1 + bf1) -> sH1 (16 rows/warp)
//   warps 4-7: gather G^T[f][t] = yj*yk*mask -> sGT (thread per f)
//   all 8:     stage-2 MMA  P[f,g] += G^T @ H1  (32x64 reg tile/warp)
// ---------------------------------------------------------------------------
__global__ __launch_bounds__(256, 2) void cfconv_mma(
    const float* __restrict__ r_ij,
    const float* __restrict__ mask,
    const float* __restrict__ Wf1,
    const float* __restrict__ bf1,
    const float* __restrict__ Wf2,
    const float* __restrict__ bf2,
    const float* __restrict__ Wout,
    const float* __restrict__ bout,
    const int*   __restrict__ nbr_j,
    const int*   __restrict__ nbr_k,
    float*       __restrict__ out)
{
    extern __shared__ float sm[];
    uint32_t* smu = (uint32_t*)sm;
    const uint32_t sb = smem_u32(sm);

    const int tid  = threadIdx.x;
    const int wid  = tid >> 5;
    const int lane = tid & 31;
    const int gr   = lane >> 2;
    const int t4   = lane & 3;
    const int ba   = blockIdx.x;
    const int b    = ba / A_;

    // zero RS pad cols [25,32) for both buffers (never rewritten)
    for (int i = tid; i < 2 * TBLK * 7; i += 256) {
        int buf = i / (TBLK * 7);
        int k = i - buf * (TBLK * 7);
        int t = k / 7, r = 25 + (k - t * 7);
        sm[OFF_RS + buf * BUFR + t * 36 + r] = 0.0f;
    }
    issue_prefetch(sb, tid, (uint32_t)ba * T_, 0, r_ij, nbr_j, nbr_k, mask);

    // one-time weights
    for (int i = tid; i < 32 * F_; i += 256) {
        int k = i >> 7, g = i & 127;
        float v = (k < RBF_) ? Wf1[k * F_ + g] : 0.0f;
        smu[OFF_WF1 + k * 136 + g] = f2t(v);
    }
    if (tid < 128) sm[OFF_BF1 + tid] = bf1[tid];

    // stage-2 tile per warp: f-rows [wm*32,+32), g-cols [wn*64,+64)
    const int wm = wid & 3, wn = wid >> 2;
    const int m0 = wm * 32, n0 = wn * 64;
    float P[2][8][4];
#pragma unroll
    for (int mt = 0; mt < 2; mt++)
#pragma unroll
        for (int nt = 0; nt < 8; nt++)
#pragma unroll
            for (int j = 0; j < 4; j++) P[mt][nt][j] = 0.0f;

    const uint32_t* gA0 = &smu[OFF_GT + (m0 + gr) * 68 + t4];
    const uint32_t* gA1 = gA0 + 8 * 68;
    const uint32_t* gA2 = gA0 + 16 * 68;
    const uint32_t* gA3 = gA0 + 24 * 68;
    const uint32_t* hB  = &smu[OFF_H1 + t4 * 136 + n0 + gr];

    float gsum = 0.0f;

    CP_WAIT0();
    __syncthreads();

    for (int blk = 0; blk < NBLK; blk++) {
        const int par = blk & 1;

        if (tid < 128) {
            // ===== stage 1: H1 = ssp(R @ Wf1 + bf1), 16 rows/warp =====
            const int tb = wid * 16;
            const uint32_t rsO = OFF_RS + (uint32_t)par * BUFR;
            const uint32_t* rA = &smu[rsO + (tb + gr) * 36 + t4];
            const uint32_t* rB = &smu[rsO + (tb + gr + 8) * 36 + t4];
            uint32_t a[4][4];
#pragma unroll
            for (int k = 0; k < 4; k++) {
                a[k][0] = rA[k * 8];
                a[k][1] = rB[k * 8];
                a[k][2] = rA[k * 8 + 4];
                a[k][3] = rB[k * 8 + 4];
            }
            const uint32_t h0 = OFF_H1 + (tb + gr) * 136;
            const uint32_t h1r = h0 + 8 * 136;
#pragma unroll
            for (int nt = 0; nt < 16; nt++) {
                float s[4] = {0.f, 0.f, 0.f, 0.f};
                const uint32_t* wB = &smu[OFF_WF1 + t4 * 136 + nt * 8 + gr];
#pragma unroll
                for (int k = 0; k < 4; k++)
                    mma8(s, a[k], wB[(k * 8) * 136], wB[(k * 8 + 4) * 136]);
                int c = nt * 8 + 2 * t4;
                float bc0 = sm[OFF_BF1 + c];
                float bc1 = sm[OFF_BF1 + c + 1];
                smu[h0 + c]      = f2t(ssp(s[0] + bc0));
                smu[h0 + c + 1]  = f2t(ssp(s[1] + bc1));
                smu[h1r + c]     = f2t(ssp(s[2] + bc0));
                smu[h1r + c + 1] = f2t(ssp(s[3] + bc1));
            }
        } else {
            // ===== gather: thread per f, all 64 t's, batched LDG =====
            const uint32_t f = tid - 128;
            const float* yb  = g_y + (uint32_t)b * (A_ * F_) + f;
            const int*   sNj = (const int*)(sm + OFF_NJ + par * 64);
            const int*   sNk = (const int*)(sm + OFF_NK + par * 64);
            const float* sM  = sm + OFF_MSK + par * 64;
#pragma unroll
            for (int tt = 0; tt < TBLK; tt += 8) {
                float vj[8], vk[8];
#pragma unroll
                for (int w = 0; w < 8; w++) {
                    vj[w] = yb[(uint32_t)sNj[tt + w] * F_];
                    vk[w] = yb[(uint32_t)sNk[tt + w] * F_];
                }
                uint4 q0, q1;
                uint32_t* g0 = (uint32_t*)&q0;
                uint32_t* g1 = (uint32_t*)&q1;
#pragma unroll
                for (int w = 0; w < 8; w++) {
                    float gv = vj[w] * vk[w] * sM[tt + w];
                    gsum += gv;
                    if (w < 4) g0[w] = f2t(gv);
                    else       g1[w - 4] = f2t(gv);
                }
                *(uint4*)&smu[OFF_GT + f * 68 + tt]     = q0;
                *(uint4*)&smu[OFF_GT + f * 68 + tt + 4] = q1;
            }
        }
        __syncthreads();

        if (blk + 1 < NBLK)
            issue_prefetch(sb, tid, (uint32_t)ba * T_ + (blk + 1) * TBLK,
                           par ^ 1, r_ij, nbr_j, nbr_k, mask);

        // ===== stage 2: P += G^T @ H1 (K=64), all 8 warps =====
#pragma unroll
        for (int k = 0; k < 8; k++) {
            const int kk = k * 8;
            uint32_t a0[4], a1[4];
            a0[0] = gA0[kk]; a0[1] = gA1[kk];
            a0[2] = gA0[kk + 4]; a0[3] = gA1[kk + 4];
            a1[0] = gA2[kk]; a1[1] = gA3[kk];
            a1[2] = gA2[kk + 4]; a1[3] = gA3[kk + 4];
#pragma unroll
            for (int nt = 0; nt < 8; nt++) {
                uint32_t b0 = hB[kk * 136 + nt * 8];
                uint32_t b1 = hB[(kk + 4) * 136 + nt * 8];
                mma8(P[0][nt], a0, b0, b1);
                mma8(P[1][nt], a1, b0, b1);
            }
        }
        CP_WAIT0();
        __syncthreads();
    }

    // ---- epilogue ----
    if (tid >= 128) sm[OFF_GS + (tid - 128)] = gsum;
    __syncthreads();
    // Wf2[g][f] overlay into contiguous H1..GT region (17408 >= 16384)
    for (int i = tid; i < F_ * F_; i += 256) sm[OFF_H1 + i] = Wf2[i];
    __syncthreads();

#pragma unroll
    for (int mt = 0; mt < 2; mt++) {
        int f0 = m0 + mt * 16 + gr;
        int f1 = f0 + 8;
        float p0 = 0.0f, p1 = 0.0f;
#pragma unroll
        for (int nt = 0; nt < 8; nt++) {
            int c = n0 + nt * 8 + 2 * t4;
            p0 += P[mt][nt][0] * sm[OFF_H1 + c * F_ + f0]
                + P[mt][nt][1] * sm[OFF_H1 + (c + 1) * F_ + f0];
            p1 += P[mt][nt][2] * sm[OFF_H1 + c * F_ + f1]
                + P[mt][nt][3] * sm[OFF_H1 + (c + 1) * F_ + f1];
        }
        p0 += __shfl_xor_sync(0xFFFFFFFFu, p0, 1);
        p0 += __shfl_xor_sync(0xFFFFFFFFu, p0, 2);
        p1 += __shfl_xor_sync(0xFFFFFFFFu, p1, 1);
        p1 += __shfl_xor_sync(0xFFFFFFFFu, p1, 2);
        if (t4 == 0) {
            sm[OFF_PRT + wn * F_ + f0] = p0;
            sm[OFF_PRT + wn * F_ + f1] = p1;
        }
    }
    __syncthreads();

    if (tid < 128) {
        float acc = sm[OFF_PRT + tid] + sm[OFF_PRT + F_ + tid]
                  + bf2[tid] * sm[OFF_GS + tid];
        sm[OFF_ACC + tid] = acc;
    }
    __syncthreads();

    if (tid < 128) {
        float o = bout[tid];
#pragma unroll 8
        for (int g = 0; g < F_; g++)
            o = fmaf(sm[OFF_ACC + g], Wout[g * F_ + tid], o);
        out[(uint32_t)ba * F_ + tid] = ssp(o);
    }
}

// ---------------------------------------------------------------------------
extern "C" void kernel_launch(void* const* d_in, const int* in_sizes, int n_in,
                              void* d_out, int out_size)
{
    const float* x     = (const float*)d_in[0];
    const float* r_ij  = (const float*)d_in[1];
    const float* mask  = (const float*)d_in[2];
    const float* Wf1   = (const float*)d_in[3];
    const float* bf1   = (const float*)d_in[4];
    const float* Wf2   = (const float*)d_in[5];
    const float* bf2   = (const float*)d_in[6];
    const float* Win   = (const float*)d_in[7];
    const float* Wout  = (const float*)d_in[8];
    const float* bout  = (const float*)d_in[9];
    const int*   nbr_j = (const int*)d_in[10];
    const int*   nbr_k = (const int*)d_in[11];
    float* out = (float*)d_out;

    cudaFuncSetAttribute(cfconv_mma,
                         cudaFuncAttributeMaxDynamicSharedMemorySize,
                         SMEM_BYTES);

    y_kernel<<<B_ * A_, 128>>>(x, Win);
    cfconv_mma<<<B_ * A_, 256, SMEM_BYTES>>>(
        r_ij, mask, Wf1, bf1, Wf2, bf2, Wout, bout, nbr_j, nbr_k, out);
}